// round 10
// baseline (speedup 1.0000x reference)
#include <cuda_runtime.h>

#define KK 21
#define LDIM 256
#define CDIM 256
#define BDIM 4
#define EDGES 255
#define SLAB_P (EDGES*CDIM)          // 65280
#define SLAB_U (LDIM*CDIM)           // 65536
#define S_ELEMS (BDIM*KK*LDIM*CDIM)  // 5,505,024
#define P_ELEMS (BDIM*KK*KK*EDGES*CDIM) // 115,153,920

// Scratch (device globals: no allocation allowed)
__device__ float g_PhT[P_ELEMS];   // pairwise_h transposed: [B,K,K, w(255), h(256)]
__device__ float g_UhT[S_ELEMS];   // unary_h transposed:    [B,K, w, h]
__device__ float g_alpha[2][S_ELEMS];  // [dir][b,k,step,chain]  dir0=h, dir1=v
__device__ float g_beta[2][S_ELEMS];

__device__ __forceinline__ float ex2f(float x){ float y; asm("ex2.approx.f32 %0, %1;" : "=f"(y) : "f"(x)); return y; }
__device__ __forceinline__ float lg2f(float x){ float y; asm("lg2.approx.f32 %0, %1;" : "=f"(y) : "f"(x)); return y; }

// ---------------------------------------------------------------------------
// Tiled transpose of [slabs][256 rows][cols] -> [slabs][cols][256]
// which==0: out = g_PhT (cols=255), which==1: out = g_UhT (cols=256)
// ---------------------------------------------------------------------------
__global__ void transpose_kernel(const float* __restrict__ in, int which, int cols) {
    __shared__ float tile[32][33];
    int slab = blockIdx.z;
    int c0 = blockIdx.x * 32, r0 = blockIdx.y * 32;
    int tx = threadIdx.x, ty = threadIdx.y;
    const float* ip = in + (size_t)slab * 256 * cols;
    float* out = which ? g_UhT : g_PhT;
    float* op = out + (size_t)slab * 256 * cols;

    #pragma unroll
    for (int m = 0; m < 4; m++) {
        int r = r0 + ty + 8*m, c = c0 + tx;
        if (c < cols) tile[ty + 8*m][tx] = ip[r * cols + c];
    }
    __syncthreads();
    #pragma unroll
    for (int m = 0; m < 4; m++) {
        int c = c0 + ty + 8*m, r = r0 + tx;
        if (c < cols) op[c * 256 + r] = tile[tx][ty + 8*m];
    }
}

// ---------------------------------------------------------------------------
// Scan kernel: 128 blocks = {fwd-h, bwd-h, fwd-v, bwd-v} x 32 chain-groups.
// Block = 21 warps (one per state row) x 32 lanes (one per chain).
// State ping-pongs through smem; one barrier per step.
// ---------------------------------------------------------------------------
__global__ __launch_bounds__(672, 1)
void scan_kernel(const float* __restrict__ Pv, const float* __restrict__ Uv,
                 const float* __restrict__ gamma) {
    __shared__ float sbuf[2][KK][32];
    int wid  = threadIdx.x >> 5;      // 0..20: state row owned by this warp
    int lane = threadIdx.x & 31;
    int variant = blockIdx.x >> 5;    // 0 fwd-h, 1 bwd-h, 2 fwd-v, 3 bwd-v
    int grp = blockIdx.x & 31;
    int b = grp >> 3;
    int c = ((grp & 7) << 5) + lane;  // chain coordinate
    int isv = (variant >= 2) ? 1 : 0;
    int bwd = variant & 1;

    const float* P = isv ? Pv : g_PhT;
    const float* U = isv ? Uv : g_UhT;
    float* AB = bwd ? g_beta[isv] : g_alpha[isv];

    float g = fmaxf(gamma[0], 0.01f);
    float sc = (1.0f / g) * 1.4426950408889634f;  // 1/(g ln2)
    float gl = g * 0.6931471805599453f;           // g ln2

    int ubase = (b * KK + wid) * SLAB_U + c;

    if (!bwd) {
        // forward: own row = k = wid, sum over j (prev state)
        int pbase = (b * KK * KK + wid) * SLAB_P + c;   // + j*KK*SLAB_P + e*256
        float a0 = U[ubase];
        sbuf[0][wid][lane] = a0;
        AB[ubase] = a0;
        __syncthreads();
        int buf = 0;
        for (int i = 1; i < LDIM; i++) {
            int pe = pbase + (i - 1) * CDIM;
            float pj[KK];
            #pragma unroll
            for (int j = 0; j < KK; j++) pj[j] = P[pe + j * (KK * SLAB_P)];
            float un = U[ubase + i * CDIM];
            float aj[KK];
            #pragma unroll
            for (int j = 0; j < KK; j++) aj[j] = sbuf[buf][j][lane];
            float amax = aj[0];
            #pragma unroll
            for (int j = 1; j < KK; j++) amax = fmaxf(amax, aj[j]);
            float nm = -amax * sc;
            float e0 = 0.f, e1 = 0.f, e2 = 0.f;
            #pragma unroll
            for (int j = 0; j < KK; j++) {
                float arg = fmaf(pj[j], sc, fmaf(aj[j], sc, nm));
                float t = ex2f(arg);
                if (j % 3 == 0) e0 += t; else if (j % 3 == 1) e1 += t; else e2 += t;
            }
            float e = (e0 + e1) + e2;
            float an = fmaf(gl, lg2f(e), un + amax);
            sbuf[buf ^ 1][wid][lane] = an;
            AB[ubase + i * CDIM] = an;
            buf ^= 1;
            __syncthreads();
        }
    } else {
        // backward: own row = j = wid, sum over k (next state)
        // t_k = u_{i+1,k} + beta_{i+1,k} kept in smem
        int pbase = (b * KK * KK + wid * KK) * SLAB_P + c;  // + k*SLAB_P + e*256
        float uL = U[ubase + (LDIM - 1) * CDIM];
        sbuf[0][wid][lane] = uL;           // t at i = L-1 (beta = 0)
        AB[ubase + (LDIM - 1) * CDIM] = 0.f;
        __syncthreads();
        int buf = 0;
        for (int i = LDIM - 2; i >= 0; i--) {
            int pe = pbase + i * CDIM;
            float pk[KK];
            #pragma unroll
            for (int k2 = 0; k2 < KK; k2++) pk[k2] = P[pe + k2 * SLAB_P];
            float un = U[ubase + i * CDIM];
            float tk[KK];
            #pragma unroll
            for (int k2 = 0; k2 < KK; k2++) tk[k2] = sbuf[buf][k2][lane];
            float tmax = tk[0];
            #pragma unroll
            for (int k2 = 1; k2 < KK; k2++) tmax = fmaxf(tmax, tk[k2]);
            float nm = -tmax * sc;
            float e0 = 0.f, e1 = 0.f, e2 = 0.f;
            #pragma unroll
            for (int k2 = 0; k2 < KK; k2++) {
                float arg = fmaf(pk[k2], sc, fmaf(tk[k2], sc, nm));
                float t = ex2f(arg);
                if (k2 % 3 == 0) e0 += t; else if (k2 % 3 == 1) e1 += t; else e2 += t;
            }
            float e = (e0 + e1) + e2;
            float bn = fmaf(gl, lg2f(e), tmax);
            AB[ubase + i * CDIM] = bn;
            sbuf[buf ^ 1][wid][lane] = bn + un;
            buf ^= 1;
            __syncthreads();
        }
    }
}

// ---------------------------------------------------------------------------
// Marginal: m = softmax_k((alpha+beta)/g).
// dir: 0=h (alpha stored [b,k,w,h] -> output [b,k,h,w] needs index swap),
//      1=v (stored [b,k,h,w] -> direct).
// ---------------------------------------------------------------------------
__global__ void marg_kernel(int dir, float* __restrict__ out,
                            const float* __restrict__ gamma, int transpose_out) {
    int idx = blockIdx.x * blockDim.x + threadIdx.x;
    if (idx >= BDIM * SLAB_U) return;
    int b = idx >> 16;
    int r = idx & 65535;
    const float* A = g_alpha[dir];
    const float* Bt = g_beta[dir];
    float g = fmaxf(gamma[0], 0.01f);
    float sc = (1.0f / g) * 1.4426950408889634f;

    int base = b * KK * SLAB_U + r;
    float s[KK];
    float m = -3.0e38f;
    #pragma unroll
    for (int k = 0; k < KK; k++) {
        s[k] = A[base + k * SLAB_U] + Bt[base + k * SLAB_U];
        m = fmaxf(m, s[k]);
    }
    float nm = -m * sc;
    float sum = 0.f;
    #pragma unroll
    for (int k = 0; k < KK; k++) {
        s[k] = ex2f(fmaf(s[k], sc, nm));
        sum += s[k];
    }
    float inv = __fdividef(1.0f, sum);
    int wbase;
    if (transpose_out) {
        int w = r >> 8, h = r & 255;
        wbase = b * KK * SLAB_U + h * 256 + w;
    } else {
        wbase = base;
    }
    #pragma unroll
    for (int k = 0; k < KK; k++) out[wbase + k * SLAB_U] = s[k] * inv;
}

// ---------------------------------------------------------------------------
// Combine: new_uh = uh - (mh-mv)/(2W); new_uv = uv + (mh-mv)/(2H). W=H=256.
// mh/mv already live in d_out at offsets 2S, 3S.
// ---------------------------------------------------------------------------
__global__ void combine_kernel(const float* __restrict__ uh,
                               const float* __restrict__ uv,
                               float* out) {
    int idx = blockIdx.x * blockDim.x + threadIdx.x;
    if (idx >= S_ELEMS / 4) return;
    const float4* mh = (const float4*)(out + 2 * (size_t)S_ELEMS);
    const float4* mv = (const float4*)(out + 3 * (size_t)S_ELEMS);
    float4 h4 = mh[idx], v4 = mv[idx];
    float4 u1 = ((const float4*)uh)[idx];
    float4 u2 = ((const float4*)uv)[idx];
    const float cc = 1.0f / 512.0f;
    float4 o1, o2;
    float d;
    d = (h4.x - v4.x) * cc; o1.x = u1.x - d; o2.x = u2.x + d;
    d = (h4.y - v4.y) * cc; o1.y = u1.y - d; o2.y = u2.y + d;
    d = (h4.z - v4.z) * cc; o1.z = u1.z - d; o2.z = u2.z + d;
    d = (h4.w - v4.w) * cc; o1.w = u1.w - d; o2.w = u2.w + d;
    ((float4*)out)[idx] = o1;
    ((float4*)(out + (size_t)S_ELEMS))[idx] = o2;
}

extern "C" void kernel_launch(void* const* d_in, const int* in_sizes, int n_in,
                              void* d_out, int out_size) {
    const float* uh    = (const float*)d_in[0];
    const float* uv    = (const float*)d_in[1];
    const float* ph    = (const float*)d_in[2];
    const float* pv    = (const float*)d_in[3];
    const float* gamma = (const float*)d_in[4];
    float* out = (float*)d_out;

    // 1) Transpose pairwise_h [B,K,K,H,W-1] -> [B,K,K,W-1,H]
    {
        dim3 grid(8, 8, BDIM * KK * KK);   // ceil(255/32)=8 col-tiles, 8 row-tiles
        dim3 blk(32, 8);
        transpose_kernel<<<grid, blk>>>(ph, 0, EDGES);
    }
    // 2) Transpose unary_h [B,K,H,W] -> [B,K,W,H]
    {
        dim3 grid(8, 8, BDIM * KK);
        dim3 blk(32, 8);
        transpose_kernel<<<grid, blk>>>(uh, 1, CDIM);
    }
    // 3) All four scans concurrently (fwd/bwd x h/v)
    scan_kernel<<<128, 672>>>(pv, uv, gamma);

    // 4) Marginals -> write mh (offset 2S) and mv (offset 3S) in d_out
    {
        int n = BDIM * SLAB_U;
        int blocks = (n + 255) / 256;
        marg_kernel<<<blocks, 256>>>(1, out + 3 * (size_t)S_ELEMS, gamma, 0); // mv
        marg_kernel<<<blocks, 256>>>(0, out + 2 * (size_t)S_ELEMS, gamma, 1); // mh
    }
    // 5) Combine -> new_uh (offset 0), new_uv (offset S)
    {
        int n = S_ELEMS / 4;
        int blocks = (n + 255) / 256;
        combine_kernel<<<blocks, 256>>>(uh, uv, out);
    }
    (void)in_sizes; (void)n_in; (void)out_size;
}

// round 11
// speedup vs baseline: 1.0284x; 1.0284x over previous
#include <cuda_runtime.h>

#define KK 21
#define LDIM 256
#define CDIM 256
#define BDIM 4
#define EDGES 255
#define SLAB_P (EDGES*CDIM)          // 65280
#define SLAB_U (LDIM*CDIM)           // 65536
#define S_ELEMS (BDIM*KK*LDIM*CDIM)  // 5,505,024
#define P_ELEMS (BDIM*KK*KK*EDGES*CDIM) // 115,153,920

// Scratch (device globals: no allocation allowed)
__device__ float g_PhT[P_ELEMS];   // pairwise_h transposed: [B,K,K, w(255), h(256)]
__device__ float g_UhT[S_ELEMS];   // unary_h transposed:    [B,K, w, h]
__device__ float g_alpha[2][S_ELEMS];  // [dir][b,k,step,chain]  dir0=h, dir1=v
__device__ float g_beta[2][S_ELEMS];

__device__ __forceinline__ float ex2f(float x){ float y; asm("ex2.approx.f32 %0, %1;" : "=f"(y) : "f"(x)); return y; }
__device__ __forceinline__ float lg2f(float x){ float y; asm("lg2.approx.f32 %0, %1;" : "=f"(y) : "f"(x)); return y; }

// ---------------------------------------------------------------------------
// Tiled transpose of [slabs][256 rows][cols] -> [slabs][cols][256]
// which==0: out = g_PhT (cols=255), which==1: out = g_UhT (cols=256)
// ---------------------------------------------------------------------------
__global__ void transpose_kernel(const float* __restrict__ in, int which, int cols) {
    __shared__ float tile[32][33];
    int slab = blockIdx.z;
    int c0 = blockIdx.x * 32, r0 = blockIdx.y * 32;
    int tx = threadIdx.x, ty = threadIdx.y;
    const float* ip = in + (size_t)slab * 256 * cols;
    float* out = which ? g_UhT : g_PhT;
    float* op = out + (size_t)slab * 256 * cols;

    #pragma unroll
    for (int m = 0; m < 4; m++) {
        int r = r0 + ty + 8*m, c = c0 + tx;
        if (c < cols) tile[ty + 8*m][tx] = __ldcs(&ip[r * cols + c]);
    }
    __syncthreads();
    #pragma unroll
    for (int m = 0; m < 4; m++) {
        int c = c0 + ty + 8*m, r = r0 + tx;
        if (c < cols) __stcs(&op[c * 256 + r], tile[tx][ty + 8*m]);
    }
}

// ---------------------------------------------------------------------------
// Scan kernel: 128 blocks = {fwd-h, bwd-h, fwd-v, bwd-v} x 32 chain-groups.
// Block = 21 warps (one per state row) x 32 lanes (one per chain).
// State ping-pongs through smem; one barrier per step.
// Pairwise loads for step i+1 are prefetched into registers before the
// barrier of step i, so DRAM latency overlaps compute.
// ---------------------------------------------------------------------------
__global__ __launch_bounds__(672, 1)
void scan_kernel(const float* __restrict__ Pv, const float* __restrict__ Uv,
                 const float* __restrict__ gamma) {
    __shared__ float sbuf[2][KK][32];
    int wid  = threadIdx.x >> 5;      // 0..20: state row owned by this warp
    int lane = threadIdx.x & 31;
    int variant = blockIdx.x >> 5;    // 0 fwd-h, 1 bwd-h, 2 fwd-v, 3 bwd-v
    int grp = blockIdx.x & 31;
    int b = grp >> 3;
    int c = ((grp & 7) << 5) + lane;  // chain coordinate
    int isv = (variant >= 2) ? 1 : 0;
    int bwd = variant & 1;

    const float* P = isv ? Pv : g_PhT;
    const float* U = isv ? Uv : g_UhT;
    float* AB = bwd ? g_beta[isv] : g_alpha[isv];

    float g = fmaxf(gamma[0], 0.01f);
    float sc = (1.0f / g) * 1.4426950408889634f;  // 1/(g ln2)
    float gl = g * 0.6931471805599453f;           // g ln2

    int ubase = (b * KK + wid) * SLAB_U + c;

    if (!bwd) {
        // forward: own row = k = wid, sum over j (prev state)
        int pbase = (b * KK * KK + wid) * SLAB_P + c;   // + j*KK*SLAB_P + e*256
        float a0 = U[ubase];
        sbuf[0][wid][lane] = a0;
        AB[ubase] = a0;

        // preload edge 0 (used at i=1) and unary at i=1
        float pj[KK];
        #pragma unroll
        for (int j = 0; j < KK; j++) pj[j] = __ldcs(&P[pbase + j * (KK * SLAB_P)]);
        float un = U[ubase + CDIM];

        __syncthreads();
        int buf = 0;
        for (int i = 1; i < LDIM; i++) {
            // prefetch next step (edge i, unary i+1); clamp on last iter
            int en = (i < EDGES) ? i : (EDGES - 1);
            int pe = pbase + en * CDIM;
            float pn[KK];
            #pragma unroll
            for (int j = 0; j < KK; j++) pn[j] = __ldcs(&P[pe + j * (KK * SLAB_P)]);
            int iun = (i + 1 < LDIM) ? (i + 1) : (LDIM - 1);
            float unn = U[ubase + iun * CDIM];

            float aj[KK];
            #pragma unroll
            for (int j = 0; j < KK; j++) aj[j] = sbuf[buf][j][lane];
            float amax = aj[0];
            #pragma unroll
            for (int j = 1; j < KK; j++) amax = fmaxf(amax, aj[j]);
            float nm = -amax * sc;
            float e0 = 0.f, e1 = 0.f, e2 = 0.f;
            #pragma unroll
            for (int j = 0; j < KK; j++) {
                float arg = fmaf(pj[j], sc, fmaf(aj[j], sc, nm));
                float t = ex2f(arg);
                if (j % 3 == 0) e0 += t; else if (j % 3 == 1) e1 += t; else e2 += t;
            }
            float e = (e0 + e1) + e2;
            float an = fmaf(gl, lg2f(e), un + amax);
            sbuf[buf ^ 1][wid][lane] = an;
            AB[ubase + i * CDIM] = an;
            buf ^= 1;
            __syncthreads();

            #pragma unroll
            for (int j = 0; j < KK; j++) pj[j] = pn[j];
            un = unn;
        }
    } else {
        // backward: own row = j = wid, sum over k (next state)
        // t_k = u_{i+1,k} + beta_{i+1,k} kept in smem
        int pbase = (b * KK * KK + wid * KK) * SLAB_P + c;  // + k*SLAB_P + e*256
        float uL = U[ubase + (LDIM - 1) * CDIM];
        sbuf[0][wid][lane] = uL;           // t at i = L-1 (beta = 0)
        AB[ubase + (LDIM - 1) * CDIM] = 0.f;

        // preload edge LDIM-2 (used at i=LDIM-2) and unary at i=LDIM-2
        float pk[KK];
        {
            int pe = pbase + (LDIM - 2) * CDIM;
            #pragma unroll
            for (int k2 = 0; k2 < KK; k2++) pk[k2] = __ldcs(&P[pe + k2 * SLAB_P]);
        }
        float un = U[ubase + (LDIM - 2) * CDIM];

        __syncthreads();
        int buf = 0;
        for (int i = LDIM - 2; i >= 0; i--) {
            // prefetch next step (edge i-1, unary i-1); clamp on last iter
            int en = (i > 0) ? (i - 1) : 0;
            int pe = pbase + en * CDIM;
            float pn[KK];
            #pragma unroll
            for (int k2 = 0; k2 < KK; k2++) pn[k2] = __ldcs(&P[pe + k2 * SLAB_P]);
            float unn = U[ubase + en * CDIM];

            float tk[KK];
            #pragma unroll
            for (int k2 = 0; k2 < KK; k2++) tk[k2] = sbuf[buf][k2][lane];
            float tmax = tk[0];
            #pragma unroll
            for (int k2 = 1; k2 < KK; k2++) tmax = fmaxf(tmax, tk[k2]);
            float nm = -tmax * sc;
            float e0 = 0.f, e1 = 0.f, e2 = 0.f;
            #pragma unroll
            for (int k2 = 0; k2 < KK; k2++) {
                float arg = fmaf(pk[k2], sc, fmaf(tk[k2], sc, nm));
                float t = ex2f(arg);
                if (k2 % 3 == 0) e0 += t; else if (k2 % 3 == 1) e1 += t; else e2 += t;
            }
            float e = (e0 + e1) + e2;
            float bn = fmaf(gl, lg2f(e), tmax);
            AB[ubase + i * CDIM] = bn;
            sbuf[buf ^ 1][wid][lane] = bn + un;
            buf ^= 1;
            __syncthreads();

            #pragma unroll
            for (int k2 = 0; k2 < KK; k2++) pk[k2] = pn[k2];
            un = unn;
        }
    }
}

// ---------------------------------------------------------------------------
// Marginal for v direction (dir=1): storage [b,k,h,w] matches output layout,
// fully coalesced both ways.
// ---------------------------------------------------------------------------
__global__ void marg_v_kernel(float* __restrict__ out,
                              const float* __restrict__ gamma) {
    int idx = blockIdx.x * blockDim.x + threadIdx.x;
    if (idx >= BDIM * SLAB_U) return;
    int b = idx >> 16;
    int r = idx & 65535;
    const float* A = g_alpha[1];
    const float* Bt = g_beta[1];
    float g = fmaxf(gamma[0], 0.01f);
    float sc = (1.0f / g) * 1.4426950408889634f;

    int base = b * KK * SLAB_U + r;
    float s[KK];
    float m = -3.0e38f;
    #pragma unroll
    for (int k = 0; k < KK; k++) {
        s[k] = __ldcs(&A[base + k * SLAB_U]) + __ldcs(&Bt[base + k * SLAB_U]);
        m = fmaxf(m, s[k]);
    }
    float nm = -m * sc;
    float sum = 0.f;
    #pragma unroll
    for (int k = 0; k < KK; k++) {
        s[k] = ex2f(fmaf(s[k], sc, nm));
        sum += s[k];
    }
    float inv = __fdividef(1.0f, sum);
    #pragma unroll
    for (int k = 0; k < KK; k++) out[base + k * SLAB_U] = s[k] * inv;
}

// ---------------------------------------------------------------------------
// Marginal for h direction (dir=0): storage [b,k,w,h], output [b,k,h,w].
// Tiled 32x32 transpose through smem so reads AND writes are coalesced.
// Thread (tx,ty) computes position (w=w0+ty, h=h0+tx), writes (h=h0+ty, w=w0+tx).
// ---------------------------------------------------------------------------
__global__ __launch_bounds__(1024)
void marg_h_kernel(float* __restrict__ out,
                   const float* __restrict__ gamma) {
    __shared__ float tile[32][33];
    int b = blockIdx.z;
    int w0 = blockIdx.y * 32, h0 = blockIdx.x * 32;
    int tx = threadIdx.x, ty = threadIdx.y;
    const float* A = g_alpha[0];
    const float* Bt = g_beta[0];
    float g = fmaxf(gamma[0], 0.01f);
    float sc = (1.0f / g) * 1.4426950408889634f;

    int base = b * KK * SLAB_U + (w0 + ty) * 256 + (h0 + tx);
    float s[KK];
    float m = -3.0e38f;
    #pragma unroll
    for (int k = 0; k < KK; k++) {
        s[k] = __ldcs(&A[base + k * SLAB_U]) + __ldcs(&Bt[base + k * SLAB_U]);
        m = fmaxf(m, s[k]);
    }
    float nm = -m * sc;
    float sum = 0.f;
    #pragma unroll
    for (int k = 0; k < KK; k++) {
        s[k] = ex2f(fmaf(s[k], sc, nm));
        sum += s[k];
    }
    float inv = __fdividef(1.0f, sum);

    int wbase = b * KK * SLAB_U + (h0 + ty) * 256 + (w0 + tx);
    #pragma unroll
    for (int k = 0; k < KK; k++) {
        __syncthreads();
        tile[ty][tx] = s[k] * inv;
        __syncthreads();
        out[wbase + k * SLAB_U] = tile[tx][ty];
    }
}

// ---------------------------------------------------------------------------
// Combine: new_uh = uh - (mh-mv)/(2W); new_uv = uv + (mh-mv)/(2H). W=H=256.
// mh/mv already live in d_out at offsets 2S, 3S.
// ---------------------------------------------------------------------------
__global__ void combine_kernel(const float* __restrict__ uh,
                               const float* __restrict__ uv,
                               float* out) {
    int idx = blockIdx.x * blockDim.x + threadIdx.x;
    if (idx >= S_ELEMS / 4) return;
    const float4* mh = (const float4*)(out + 2 * (size_t)S_ELEMS);
    const float4* mv = (const float4*)(out + 3 * (size_t)S_ELEMS);
    float4 h4 = mh[idx], v4 = mv[idx];
    float4 u1 = ((const float4*)uh)[idx];
    float4 u2 = ((const float4*)uv)[idx];
    const float cc = 1.0f / 512.0f;
    float4 o1, o2;
    float d;
    d = (h4.x - v4.x) * cc; o1.x = u1.x - d; o2.x = u2.x + d;
    d = (h4.y - v4.y) * cc; o1.y = u1.y - d; o2.y = u2.y + d;
    d = (h4.z - v4.z) * cc; o1.z = u1.z - d; o2.z = u2.z + d;
    d = (h4.w - v4.w) * cc; o1.w = u1.w - d; o2.w = u2.w + d;
    ((float4*)out)[idx] = o1;
    ((float4*)(out + (size_t)S_ELEMS))[idx] = o2;
}

extern "C" void kernel_launch(void* const* d_in, const int* in_sizes, int n_in,
                              void* d_out, int out_size) {
    const float* uh    = (const float*)d_in[0];
    const float* uv    = (const float*)d_in[1];
    const float* ph    = (const float*)d_in[2];
    const float* pv    = (const float*)d_in[3];
    const float* gamma = (const float*)d_in[4];
    float* out = (float*)d_out;

    // 1) Transpose pairwise_h [B,K,K,H,W-1] -> [B,K,K,W-1,H]
    {
        dim3 grid(8, 8, BDIM * KK * KK);   // ceil(255/32)=8 col-tiles, 8 row-tiles
        dim3 blk(32, 8);
        transpose_kernel<<<grid, blk>>>(ph, 0, EDGES);
    }
    // 2) Transpose unary_h [B,K,H,W] -> [B,K,W,H]
    {
        dim3 grid(8, 8, BDIM * KK);
        dim3 blk(32, 8);
        transpose_kernel<<<grid, blk>>>(uh, 1, CDIM);
    }
    // 3) All four scans concurrently (fwd/bwd x h/v)
    scan_kernel<<<128, 672>>>(pv, uv, gamma);

    // 4) Marginals -> write mh (offset 2S) and mv (offset 3S) in d_out
    {
        int n = BDIM * SLAB_U;
        int blocks = (n + 255) / 256;
        marg_v_kernel<<<blocks, 256>>>(out + 3 * (size_t)S_ELEMS, gamma);   // mv
        dim3 grid(8, 8, BDIM);
        dim3 blk(32, 32);
        marg_h_kernel<<<grid, blk>>>(out + 2 * (size_t)S_ELEMS, gamma);     // mh
    }
    // 5) Combine -> new_uh (offset 0), new_uv (offset S)
    {
        int n = S_ELEMS / 4;
        int blocks = (n + 255) / 256;
        combine_kernel<<<blocks, 256>>>(uh, uv, out);
    }
    (void)in_sizes; (void)n_in; (void)out_size;
}

// round 12
// speedup vs baseline: 1.1581x; 1.1262x over previous
#include <cuda_runtime.h>

#define KK 21
#define LDIM 256
#define CDIM 256
#define BDIM 4
#define EDGES 255
#define SLAB_P (EDGES*CDIM)          // 65280
#define SLAB_U (LDIM*CDIM)           // 65536
#define S_ELEMS (BDIM*KK*LDIM*CDIM)  // 5,505,024
#define P_ELEMS (BDIM*KK*KK*EDGES*CDIM) // 115,153,920

// Scratch (device globals: no allocation allowed)
__device__ float g_PhT[P_ELEMS];   // pairwise_h transposed: [B,K,K, w(255), h(256)]
__device__ float g_UhT[S_ELEMS];   // unary_h transposed:    [B,K, w, h]
__device__ float g_alpha[2][S_ELEMS];  // [dir][b,k,step,chain]  dir0=h, dir1=v
__device__ float g_beta[2][S_ELEMS];

__device__ __forceinline__ float ex2f(float x){ float y; asm("ex2.approx.f32 %0, %1;" : "=f"(y) : "f"(x)); return y; }
__device__ __forceinline__ float lg2f(float x){ float y; asm("lg2.approx.f32 %0, %1;" : "=f"(y) : "f"(x)); return y; }

__device__ __forceinline__ void cp16_pred(float* dst, const float* src, unsigned pred){
    unsigned su = (unsigned)__cvta_generic_to_shared(dst);
    asm volatile("{.reg .pred p; setp.ne.u32 p, %2, 0; @p cp.async.cg.shared.global [%0], [%1], 16;}"
                 :: "r"(su), "l"(src), "r"(pred));
}

// ---------------------------------------------------------------------------
// Tiled transpose of [slabs][256 rows][cols] -> [slabs][cols][256]
// which==0: out = g_PhT (cols=255), which==1: out = g_UhT (cols=256)
// ---------------------------------------------------------------------------
__global__ void transpose_kernel(const float* __restrict__ in, int which, int cols) {
    __shared__ float tile[32][33];
    int slab = blockIdx.z;
    int c0 = blockIdx.x * 32, r0 = blockIdx.y * 32;
    int tx = threadIdx.x, ty = threadIdx.y;
    const float* ip = in + (size_t)slab * 256 * cols;
    float* out = which ? g_UhT : g_PhT;
    float* op = out + (size_t)slab * 256 * cols;

    #pragma unroll
    for (int m = 0; m < 4; m++) {
        int r = r0 + ty + 8*m, c = c0 + tx;
        if (c < cols) tile[ty + 8*m][tx] = __ldcs(&ip[r * cols + c]);
    }
    __syncthreads();
    #pragma unroll
    for (int m = 0; m < 4; m++) {
        int c = c0 + ty + 8*m, r = r0 + tx;
        if (c < cols) __stcs(&op[c * 256 + r], tile[tx][ty + 8*m]);
    }
}

// ---------------------------------------------------------------------------
// Scan: 128 blocks = {fwd-h, bwd-h, fwd-v, bwd-v} x 32 chain-groups.
// Block = 21 warps (state per warp) x 32 lanes (chain per lane).
// Depth-3 cp.async smem pipeline for pairwise + unary; single barrier/step.
// ---------------------------------------------------------------------------
template<int BWD>
__device__ __forceinline__ void scan_dir(const float* __restrict__ P,
    const float* __restrict__ U, float* __restrict__ AB,
    int b, int c0, int wid, int lane, float sc, float gl,
    float* Pb, float* Ub, float* Sb)
{
    const long RS = BWD ? (long)SLAB_P : (long)KK * SLAB_P;   // row stride in floats
    const int rowsel = BWD ? wid * KK : wid;
    const float* gP = P + ((long)(b * KK * KK) + rowsel) * SLAB_P + c0;
    const float* gU = U + ((long)(b * KK) + wid) * SLAB_U + c0;
    int subrow = lane >> 3, chunk = lane & 7;

    auto issue = [&](int s, int buf) {
        int e  = BWD ? (254 - s) : s;        // edge index
        int up = BWD ? (254 - s) : (s + 1);  // unary position
        const float* srcRow = gP + (long)e * CDIM;
        const float* srcU   = gU + (long)up * CDIM;
        #pragma unroll
        for (int q = 0; q < 6; q++) {
            int row = q * 4 + subrow;
            cp16_pred(Pb + (((buf * 21 + wid) * 21 + row) * 32 + chunk * 4),
                      srcRow + (long)row * RS + chunk * 4,
                      (unsigned)(row < KK));
        }
        cp16_pred(Ub + ((buf * 21 + wid) * 32 + chunk * 4),
                  srcU + chunk * 4,
                  (unsigned)(subrow == 0));
        asm volatile("cp.async.commit_group;" ::: "memory");
    };

    issue(0, 0);
    issue(1, 1);

    // init state
    {
        int ipos = BWD ? (LDIM - 1) : 0;
        float u0 = gU[(long)ipos * CDIM + lane];
        Sb[wid * 32 + lane] = u0;                  // fwd: alpha0=u0 ; bwd: t=0+uL
        AB[((long)(b * KK) + wid) * SLAB_U + (long)ipos * CDIM + c0 + lane] = BWD ? 0.f : u0;
    }

    int sb = 0;
    long abbase = ((long)(b * KK) + wid) * SLAB_U + c0 + lane;
    for (int s = 0; s < 255; s++) {
        int cur = s % 3;
        asm volatile("cp.async.wait_group 1;" ::: "memory");
        __syncthreads();   // step-s tile visible everywhere; prev state visible; buf (s+2)%3 free
        int nxt = s + 2; if (nxt > 254) nxt = 254;   // dup issue keeps group count uniform
        issue(nxt, (s + 2) % 3);

        float pj[KK], st[KK];
        #pragma unroll
        for (int j = 0; j < KK; j++) pj[j] = Pb[((cur * 21 + wid) * 21 + j) * 32 + lane];
        #pragma unroll
        for (int j = 0; j < KK; j++) st[j] = Sb[(sb * 21 + j) * 32 + lane];
        float un = Ub[(cur * 21 + wid) * 32 + lane];

        float mx = st[0];
        #pragma unroll
        for (int j = 1; j < KK; j++) mx = fmaxf(mx, st[j]);
        float nm = -mx * sc;
        float e0 = 0.f, e1 = 0.f, e2 = 0.f;
        #pragma unroll
        for (int j = 0; j < KK; j++) {
            float t = ex2f(fmaf(pj[j], sc, fmaf(st[j], sc, nm)));
            if (j % 3 == 0) e0 += t; else if (j % 3 == 1) e1 += t; else e2 += t;
        }
        float lse = fmaf(gl, lg2f((e0 + e1) + e2), mx);   // g*logsumexp((st+p)/g)

        int ipos = BWD ? (254 - s) : (s + 1);
        float outv, newstate;
        if (!BWD) { outv = lse + un; newstate = outv; }   // alpha_i
        else      { outv = lse;      newstate = lse + un; } // beta_i ; t = beta+u
        AB[abbase + (long)ipos * CDIM] = outv;
        Sb[((sb ^ 1) * 21 + wid) * 32 + lane] = newstate;
        sb ^= 1;
    }
    asm volatile("cp.async.wait_group 0;" ::: "memory");
}

__global__ __launch_bounds__(672, 1)
void scan_kernel(const float* __restrict__ Pv, const float* __restrict__ Uv,
                 const float* __restrict__ gamma) {
    extern __shared__ float sm[];
    float* Pb = sm;                        // [3][21][21][32]
    float* Ub = Pb + 3 * 21 * 21 * 32;     // [3][21][32]
    float* Sb = Ub + 3 * 21 * 32;          // [2][21][32]

    int wid  = threadIdx.x >> 5;
    int lane = threadIdx.x & 31;
    int variant = blockIdx.x >> 5;    // 0 fwd-h, 1 bwd-h, 2 fwd-v, 3 bwd-v
    int grp = blockIdx.x & 31;
    int b = grp >> 3;
    int c0 = (grp & 7) << 5;
    int isv = (variant >= 2) ? 1 : 0;
    int bwd = variant & 1;

    const float* P = isv ? Pv : g_PhT;
    const float* U = isv ? Uv : g_UhT;
    float* AB = bwd ? g_beta[isv] : g_alpha[isv];

    float g = fmaxf(gamma[0], 0.01f);
    float sc = (1.0f / g) * 1.4426950408889634f;  // 1/(g ln2)
    float gl = g * 0.6931471805599453f;           // g ln2

    if (bwd) scan_dir<1>(P, U, AB, b, c0, wid, lane, sc, gl, Pb, Ub, Sb);
    else     scan_dir<0>(P, U, AB, b, c0, wid, lane, sc, gl, Pb, Ub, Sb);
}

// ---------------------------------------------------------------------------
// Marginal for h direction (dir=0): storage [b,k,w,h], output [b,k,h,w].
// Tiled 32x32 transpose through smem so reads AND writes are coalesced.
// ---------------------------------------------------------------------------
__global__ __launch_bounds__(1024)
void marg_h_kernel(float* __restrict__ out,
                   const float* __restrict__ gamma) {
    __shared__ float tile[32][33];
    int b = blockIdx.z;
    int w0 = blockIdx.y * 32, h0 = blockIdx.x * 32;
    int tx = threadIdx.x, ty = threadIdx.y;
    const float* A = g_alpha[0];
    const float* Bt = g_beta[0];
    float g = fmaxf(gamma[0], 0.01f);
    float sc = (1.0f / g) * 1.4426950408889634f;

    int base = b * KK * SLAB_U + (w0 + ty) * 256 + (h0 + tx);
    float s[KK];
    float m = -3.0e38f;
    #pragma unroll
    for (int k = 0; k < KK; k++) {
        s[k] = __ldcs(&A[base + k * SLAB_U]) + __ldcs(&Bt[base + k * SLAB_U]);
        m = fmaxf(m, s[k]);
    }
    float nm = -m * sc;
    float sum = 0.f;
    #pragma unroll
    for (int k = 0; k < KK; k++) {
        s[k] = ex2f(fmaf(s[k], sc, nm));
        sum += s[k];
    }
    float inv = __fdividef(1.0f, sum);

    int wbase = b * KK * SLAB_U + (h0 + ty) * 256 + (w0 + tx);
    #pragma unroll
    for (int k = 0; k < KK; k++) {
        __syncthreads();
        tile[ty][tx] = s[k] * inv;
        __syncthreads();
        out[wbase + k * SLAB_U] = tile[tx][ty];
    }
}

// ---------------------------------------------------------------------------
// Marginal for v direction fused with combine. Runs AFTER marg_h.
// Computes mv (coalesced layout), then new_uh = uh - (mh-mv)/512,
// new_uv = uv + (mh-mv)/512, reading mh from out (L2-warm).
// ---------------------------------------------------------------------------
__global__ void marg_v_combine_kernel(const float* __restrict__ uh,
                                      const float* __restrict__ uv,
                                      float* __restrict__ out,
                                      const float* __restrict__ gamma) {
    int idx = blockIdx.x * blockDim.x + threadIdx.x;
    if (idx >= BDIM * SLAB_U) return;
    int b = idx >> 16;
    int r = idx & 65535;
    const float* A = g_alpha[1];
    const float* Bt = g_beta[1];
    float g = fmaxf(gamma[0], 0.01f);
    float sc = (1.0f / g) * 1.4426950408889634f;

    int base = b * KK * SLAB_U + r;
    float s[KK];
    float m = -3.0e38f;
    #pragma unroll
    for (int k = 0; k < KK; k++) {
        s[k] = __ldcs(&A[base + k * SLAB_U]) + __ldcs(&Bt[base + k * SLAB_U]);
        m = fmaxf(m, s[k]);
    }
    float nm = -m * sc;
    float sum = 0.f;
    #pragma unroll
    for (int k = 0; k < KK; k++) {
        s[k] = ex2f(fmaf(s[k], sc, nm));
        sum += s[k];
    }
    float inv = __fdividef(1.0f, sum);

    const float* mh   = out + 2 * (size_t)S_ELEMS;
    float* mv_out     = out + 3 * (size_t)S_ELEMS;
    const float cc = 1.0f / 512.0f;
    #pragma unroll
    for (int k = 0; k < KK; k++) {
        int o = base + k * SLAB_U;
        float mvv = s[k] * inv;
        mv_out[o] = mvv;
        float d = (mh[o] - mvv) * cc;
        out[o] = uh[o] - d;                          // new_uh
        out[o + (size_t)S_ELEMS] = uv[o] + d;        // new_uv
    }
}

extern "C" void kernel_launch(void* const* d_in, const int* in_sizes, int n_in,
                              void* d_out, int out_size) {
    const float* uh    = (const float*)d_in[0];
    const float* uv    = (const float*)d_in[1];
    const float* ph    = (const float*)d_in[2];
    const float* pv    = (const float*)d_in[3];
    const float* gamma = (const float*)d_in[4];
    float* out = (float*)d_out;

    // 1) Transpose pairwise_h [B,K,K,H,W-1] -> [B,K,K,W-1,H]
    {
        dim3 grid(8, 8, BDIM * KK * KK);
        dim3 blk(32, 8);
        transpose_kernel<<<grid, blk>>>(ph, 0, EDGES);
    }
    // 2) Transpose unary_h [B,K,H,W] -> [B,K,W,H]
    {
        dim3 grid(8, 8, BDIM * KK);
        dim3 blk(32, 8);
        transpose_kernel<<<grid, blk>>>(uh, 1, CDIM);
    }
    // 3) All four scans concurrently with deep cp.async pipeline
    {
        const int smem_bytes = (3*21*21*32 + 3*21*32 + 2*21*32) * 4;  // 182,784
        cudaFuncSetAttribute(scan_kernel, cudaFuncAttributeMaxDynamicSharedMemorySize, smem_bytes);
        scan_kernel<<<128, 672, smem_bytes>>>(pv, uv, gamma);
    }
    // 4) mh (offset 2S) via tiled-transpose marginal
    {
        dim3 grid(8, 8, BDIM);
        dim3 blk(32, 32);
        marg_h_kernel<<<grid, blk>>>(out + 2 * (size_t)S_ELEMS, gamma);
    }
    // 5) mv (offset 3S) + combine -> new_uh (0), new_uv (S)
    {
        int n = BDIM * SLAB_U;
        int blocks = (n + 255) / 256;
        marg_v_combine_kernel<<<blocks, 256>>>(uh, uv, out, gamma);
    }
    (void)in_sizes; (void)n_in; (void)out_size;
}